// round 4
// baseline (speedup 1.0000x reference)
#include <cuda_runtime.h>

#define L_MAX   2048
#define BATCH   64
#define DDIM    256
#define CCH     512
#define NCHUNK  16
#define ROWS_PER_CHUNK (L_MAX / NCHUNK)   // 128
#define ROWS_PER_WARP  (ROWS_PER_CHUNK / 8) // 16

#define HQ_BLOCKS 2048
#define M_BLOCKS  96

// ---- scratch (no allocations allowed) ----
__device__ float g_hq[BATCH * DDIM];
__device__ float g_M[3 * DDIM];
__device__ float g_hardU[L_MAX * BATCH];
__device__ float g_part[BATCH * NCHUNK * DDIM];
__device__ float g_denp[BATCH * NCHUNK];

__device__ __forceinline__ float ftanh(float x) {
    float e = __expf(2.0f * x);
    return 1.0f - __fdividef(2.0f, e + 1.0f);
}

// ---------------------------------------------------------------------------
// Kernel 1: prep (warp-per-output, fully coalesced). Unchanged from R3.
// ---------------------------------------------------------------------------
__global__ __launch_bounds__(256) void prep_kernel(
    const float* __restrict__ ht, const float* __restrict__ Wq,
    const float* __restrict__ Wap, const float* __restrict__ Wc,
    const float* __restrict__ bap)
{
    int warp = threadIdx.x >> 5, lane = threadIdx.x & 31;

    if (blockIdx.x < HQ_BLOCKS) {
        int gw = blockIdx.x * 8 + warp;
        int b = gw >> 8;
        int d = gw & 255;
        const float* htr = ht + b * DDIM;
        const float* wqr = Wq + (size_t)d * DDIM;
        float a = 0.f;
#pragma unroll
        for (int i = 0; i < DDIM / 32; i++) {
            int e = lane + 32 * i;
            a += htr[e] * wqr[e];
        }
#pragma unroll
        for (int off = 16; off; off >>= 1)
            a += __shfl_xor_sync(0xffffffffu, a, off);
        if (lane == 0) g_hq[b * DDIM + d] = a + bap[d];
    } else {
        int gw = (blockIdx.x - HQ_BLOCKS) * 8 + warp;
        int dd = gw / 3;
        int k  = gw % 3;
        const float* wr = Wap + (size_t)dd * CCH;
        float m = 0.f;
#pragma unroll
        for (int i = 0; i < CCH / 32; i++) {
            int c = lane + 32 * i;
            m += wr[c] * Wc[c * 3 + k];
        }
#pragma unroll
        for (int off = 16; off; off >>= 1)
            m += __shfl_xor_sync(0xffffffffu, m, off);
        if (lane == 0) g_M[k * DDIM + dd] = m;
    }
}

// ---------------------------------------------------------------------------
// Kernel 2: main, two-phase.
//   Phase 1: warp-per-row scoring, rows batched x4 for MLP. h -> s_h + g_hardU.
//   Phase 2: thread-per-column val accumulation, predicate from shared.
// ---------------------------------------------------------------------------
__global__ __launch_bounds__(256) void main_kernel(
    const float* __restrict__ ctx_val, const float* __restrict__ ctx_key,
    const float* __restrict__ ctx_mask, const float* __restrict__ past,
    const float* __restrict__ W_attn, const float* __restrict__ b_attn)
{
    __shared__ float s_h[ROWS_PER_CHUNK];   // unnormalized hard per row

    int b = blockIdx.y, chunk = blockIdx.x;
    int w = threadIdx.x >> 5, lane = threadIdx.x & 31;
    int d0 = lane * 4;
    int d1 = 128 + lane * 4;

    float4 hq0 = *reinterpret_cast<const float4*>(&g_hq[b * DDIM + d0]);
    float4 hq1 = *reinterpret_cast<const float4*>(&g_hq[b * DDIM + d1]);
    float4 M00 = *reinterpret_cast<const float4*>(&g_M[d0]);
    float4 M01 = *reinterpret_cast<const float4*>(&g_M[d1]);
    float4 M10 = *reinterpret_cast<const float4*>(&g_M[DDIM + d0]);
    float4 M11 = *reinterpret_cast<const float4*>(&g_M[DDIM + d1]);
    float4 M20 = *reinterpret_cast<const float4*>(&g_M[2 * DDIM + d0]);
    float4 M21 = *reinterpret_cast<const float4*>(&g_M[2 * DDIM + d1]);
    float4 Wa0 = *reinterpret_cast<const float4*>(&W_attn[d0]);
    float4 Wa1 = *reinterpret_cast<const float4*>(&W_attn[d1]);
    float ba = b_attn[0];

    // ---- Phase 1: scores for this warp's 16 rows, batched 4 at a time ----
    int lbase = chunk * ROWS_PER_CHUNK + w * ROWS_PER_WARP;
#pragma unroll
    for (int rb = 0; rb < ROWS_PER_WARP / 4; rb++) {
        int l0 = lbase + rb * 4;
        float4 ka[4], kb[4];
#pragma unroll
        for (int j = 0; j < 4; j++) {
            size_t row = ((size_t)(l0 + j) * BATCH + b) * DDIM;
            ka[j] = *reinterpret_cast<const float4*>(ctx_key + row + d0);
            kb[j] = *reinterpret_cast<const float4*>(ctx_key + row + d1);
        }
        float sc[4];
#pragma unroll
        for (int j = 0; j < 4; j++) {
            int l = l0 + j;
            float pm = (l > 0)         ? past[b * L_MAX + l - 1] : 0.f;
            float p0 =                   past[b * L_MAX + l];
            float pp = (l < L_MAX - 1) ? past[b * L_MAX + l + 1] : 0.f;
            float s;
            s  = Wa0.x * ftanh(ka[j].x + hq0.x + pm * M00.x + p0 * M10.x + pp * M20.x);
            s += Wa0.y * ftanh(ka[j].y + hq0.y + pm * M00.y + p0 * M10.y + pp * M20.y);
            s += Wa0.z * ftanh(ka[j].z + hq0.z + pm * M00.z + p0 * M10.z + pp * M20.z);
            s += Wa0.w * ftanh(ka[j].w + hq0.w + pm * M00.w + p0 * M10.w + pp * M20.w);
            s += Wa1.x * ftanh(kb[j].x + hq1.x + pm * M01.x + p0 * M11.x + pp * M21.x);
            s += Wa1.y * ftanh(kb[j].y + hq1.y + pm * M01.y + p0 * M11.y + pp * M21.y);
            s += Wa1.z * ftanh(kb[j].z + hq1.z + pm * M01.z + p0 * M11.z + pp * M21.z);
            s += Wa1.w * ftanh(kb[j].w + hq1.w + pm * M01.w + p0 * M11.w + pp * M21.w);
            sc[j] = s;
        }
#pragma unroll
        for (int off = 16; off; off >>= 1) {
#pragma unroll
            for (int j = 0; j < 4; j++)
                sc[j] += __shfl_xor_sync(0xffffffffu, sc[j], off);
        }
        if (lane == 0) {
#pragma unroll
            for (int j = 0; j < 4; j++) {
                int l = l0 + j;
                float h = (sc[j] + ba >= 0.f) ? ctx_mask[l * BATCH + b] : 0.f;
                s_h[w * ROWS_PER_WARP + rb * 4 + j] = h;
                g_hardU[l * BATCH + b] = h;
            }
        }
    }
    __syncthreads();

    // ---- Phase 2: thread-per-column accumulation over 128 rows ----
    {
        int d = threadIdx.x;
        const float* vbase = ctx_val +
            ((size_t)chunk * ROWS_PER_CHUNK * BATCH + b) * DDIM + d;
        float acc = 0.f;
#pragma unroll 8
        for (int r = 0; r < ROWS_PER_CHUNK; r++) {
            float h = s_h[r];
            if (h != 0.f)
                acc += h * vbase[(size_t)r * (BATCH * DDIM)];
        }
        g_part[((size_t)b * NCHUNK + chunk) * DDIM + d] = acc;
    }

    // per-chunk hard sum (warp 0)
    if (threadIdx.x < 32) {
        float c = 0.f;
#pragma unroll
        for (int r = 0; r < ROWS_PER_CHUNK / 32; r++)
            c += s_h[lane + 32 * r];
#pragma unroll
        for (int off = 16; off; off >>= 1)
            c += __shfl_xor_sync(0xffffffffu, c, off);
        if (lane == 0) g_denp[b * NCHUNK + chunk] = c;
    }
}

// ---------------------------------------------------------------------------
// Kernel 3: finish. Normalize; out = concat(ct.flat, hard.flat)
// ---------------------------------------------------------------------------
__global__ __launch_bounds__(256) void finish_kernel(float* __restrict__ out)
{
    int i = blockIdx.x * blockDim.x + threadIdx.x;
    if (i < BATCH * DDIM) {
        int b = i >> 8;
        int d = i & (DDIM - 1);
        float den = 0.f;
#pragma unroll
        for (int c = 0; c < NCHUNK; c++) den += g_denp[b * NCHUNK + c];
        float ct = 0.f;
#pragma unroll
        for (int c = 0; c < NCHUNK; c++)
            ct += g_part[((size_t)b * NCHUNK + c) * DDIM + d];
        out[i] = ct / (den + 1e-10f);
    } else if (i < BATCH * DDIM + L_MAX * BATCH) {
        int j = i - BATCH * DDIM;
        int b = j & (BATCH - 1);
        float den = 0.f;
#pragma unroll
        for (int c = 0; c < NCHUNK; c++) den += g_denp[b * NCHUNK + c];
        out[i] = g_hardU[j] / (den + 1e-10f);
    }
}

// ---------------------------------------------------------------------------
extern "C" void kernel_launch(void* const* d_in, const int* in_sizes, int n_in,
                              void* d_out, int out_size)
{
    (void)in_sizes; (void)n_in; (void)out_size;
    const float* ctx_val  = (const float*)d_in[0];
    const float* ctx_key  = (const float*)d_in[1];
    const float* ctx_mask = (const float*)d_in[2];
    const float* past     = (const float*)d_in[3];
    const float* ht       = (const float*)d_in[4];
    const float* Wc       = (const float*)d_in[5];
    const float* Wq       = (const float*)d_in[6];
    const float* Wap      = (const float*)d_in[7];
    const float* bap      = (const float*)d_in[8];
    const float* Wattn    = (const float*)d_in[9];
    const float* battn    = (const float*)d_in[10];
    float* out = (float*)d_out;

    prep_kernel<<<HQ_BLOCKS + M_BLOCKS, 256>>>(ht, Wq, Wap, Wc, bap);

    dim3 grid(NCHUNK, BATCH);
    main_kernel<<<grid, 256>>>(ctx_val, ctx_key, ctx_mask, past, Wattn, battn);

    int total = BATCH * DDIM + L_MAX * BATCH;
    finish_kernel<<<(total + 255) / 256, 256>>>(out);
}